// round 3
// baseline (speedup 1.0000x reference)
#include <cuda_runtime.h>

// REINFORCE fused kernel, GB300 sm_103a
//
// out[0:T)      = generator_objective  (atomic column reduction)
// out[T:T+B*T)  = cumulative_rewards   (row-major [B,T])
//
// Phase A: per-row reverse discounted suffix scan (warp+block scan with
//          ratio gamma^8 / gamma^256), writes cum, accumulates
//          colsum(cum - baseline) via per-block register accumulation +
//          one atomicAdd per column per block.
// Phase B: streams cum/base/log_probs, computes centered clipped advantage,
//          atomic column reduction into out[0:T).

namespace {
constexpr int   Bn     = 4096;
constexpr int   Tn     = 2048;
constexpr float GAMMA  = 0.99f;
constexpr float CLIPV  = 5.0f;
constexpr int   TPB    = 256;   // threads per block; thread k owns cols [8k, 8k+8)
constexpr int   ROWS_A = 8;     // rows per block, phase A
constexpr int   ROWS_B = 8;     // rows per block, phase B
constexpr int   NWARP  = TPB / 32;
}

__device__ float g_colsum[Tn];  // sum over batch of (cum - baseline)

__device__ __forceinline__ float log_sigmoid(float x) {
    // log(sigmoid(x)) = min(x,0) - log1p(exp(-|x|)), numerically stable
    return fminf(x, 0.f) - log1pf(__expf(-fabsf(x)));
}

__global__ void zero_kernel(float* __restrict__ obj) {
    int i = blockIdx.x * blockDim.x + threadIdx.x;
    if (i < Tn) {
        obj[i] = 0.f;
        g_colsum[i] = 0.f;
    }
}

__global__ __launch_bounds__(TPB) void phaseA_kernel(
    const float* __restrict__ logits,
    const float* __restrict__ weight,
    const float* __restrict__ base,
    float* __restrict__ out)
{
    __shared__ float Wsh[NWARP];

    const int tid  = threadIdx.x;
    const int lane = tid & 31;
    const int warp = tid >> 5;
    const int col0 = tid * 8;
    const int row0 = blockIdx.x * ROWS_A;

    // gamma powers gp[i] = gamma^i, i in [0,8]
    float gp[9];
    gp[0] = 1.f;
    #pragma unroll
    for (int i = 1; i <= 8; i++) gp[i] = gp[i - 1] * GAMMA;

    const float r8  = gp[8];           // gamma^8  (chunk ratio)
    const float s1  = r8;
    const float s2  = s1 * s1;
    const float s4  = s2 * s2;
    const float s8  = s4 * s4;
    const float s16 = s8 * s8;
    const float r256 = s16 * s16;      // gamma^256 (warp ratio)

    // r8^(31-lane), computed once
    float r8p31 = 1.f;
    for (int i = 0; i < 31 - lane; i++) r8p31 *= r8;

    float dacc[8];
    #pragma unroll
    for (int j = 0; j < 8; j++) dacc[j] = 0.f;

    float* __restrict__ cumout = out + Tn;

    for (int r = 0; r < ROWS_A; r++) {
        const long off = (long)(row0 + r) * Tn + col0;

        const float4 l0 = *(const float4*)(logits + off);
        const float4 l1 = *(const float4*)(logits + off + 4);
        const float4 w0 = *(const float4*)(weight + off);
        const float4 w1 = *(const float4*)(weight + off + 4);

        float wr[8];
        wr[0] = w0.x * log_sigmoid(l0.x);
        wr[1] = w0.y * log_sigmoid(l0.y);
        wr[2] = w0.z * log_sigmoid(l0.z);
        wr[3] = w0.w * log_sigmoid(l0.w);
        wr[4] = w1.x * log_sigmoid(l1.x);
        wr[5] = w1.y * log_sigmoid(l1.y);
        wr[6] = w1.z * log_sigmoid(l1.z);
        wr[7] = w1.w * log_sigmoid(l1.w);

        // local reverse suffix within the 8-element chunk
        float ls[8];
        ls[7] = wr[7];
        #pragma unroll
        for (int j = 6; j >= 0; j--) ls[j] = wr[j] + GAMMA * ls[j + 1];

        // warp-level inclusive suffix scan over chunk totals, ratio gamma^8
        float v = ls[0];
        {
            float o;
            o = __shfl_down_sync(0xffffffffu, v, 1);  if (lane + 1  < 32) v += s1  * o;
            o = __shfl_down_sync(0xffffffffu, v, 2);  if (lane + 2  < 32) v += s2  * o;
            o = __shfl_down_sync(0xffffffffu, v, 4);  if (lane + 4  < 32) v += s4  * o;
            o = __shfl_down_sync(0xffffffffu, v, 8);  if (lane + 8  < 32) v += s8  * o;
            o = __shfl_down_sync(0xffffffffu, v, 16); if (lane + 16 < 32) v += s16 * o;
        }
        float vnext = __shfl_down_sync(0xffffffffu, v, 1);
        if (lane == 31) vnext = 0.f;

        __syncthreads();                 // previous row's Wsh reads done
        if (lane == 0) Wsh[warp] = v;    // warp total: sum over its 32 chunks
        __syncthreads();

        // inclusive suffix over LATER warps, ratio gamma^256
        float swn = 0.f;
        for (int u = NWARP - 1; u > warp; u--) swn = Wsh[u] + r256 * swn;

        // carry into this chunk = full cum at time (col0 + 8)
        const float C = vnext + r8p31 * swn;

        float cm[8];
        #pragma unroll
        for (int j = 0; j < 8; j++) cm[j] = ls[j] + gp[8 - j] * C;

        *(float4*)(cumout + off)     = make_float4(cm[0], cm[1], cm[2], cm[3]);
        *(float4*)(cumout + off + 4) = make_float4(cm[4], cm[5], cm[6], cm[7]);

        const float4 b0 = *(const float4*)(base + off);
        const float4 b1 = *(const float4*)(base + off + 4);
        dacc[0] += cm[0] - b0.x;
        dacc[1] += cm[1] - b0.y;
        dacc[2] += cm[2] - b0.z;
        dacc[3] += cm[3] - b0.w;
        dacc[4] += cm[4] - b1.x;
        dacc[5] += cm[5] - b1.y;
        dacc[6] += cm[6] - b1.z;
        dacc[7] += cm[7] - b1.w;
    }

    #pragma unroll
    for (int j = 0; j < 8; j++)
        atomicAdd(&g_colsum[col0 + j], dacc[j]);
}

__global__ __launch_bounds__(TPB) void phaseB_kernel(
    const float* __restrict__ cum,
    const float* __restrict__ base,
    const float* __restrict__ logp,
    float* __restrict__ obj)
{
    const int tid  = threadIdx.x;
    const int col0 = tid * 8;
    const int row0 = blockIdx.x * ROWS_B;

    float mean[8];
    #pragma unroll
    for (int j = 0; j < 8; j++) mean[j] = g_colsum[col0 + j] * (1.f / Bn);

    float oacc[8];
    #pragma unroll
    for (int j = 0; j < 8; j++) oacc[j] = 0.f;

    for (int r = 0; r < ROWS_B; r++) {
        const long off = (long)(row0 + r) * Tn + col0;

        const float4 c0 = *(const float4*)(cum + off);
        const float4 c1 = *(const float4*)(cum + off + 4);
        const float4 b0 = *(const float4*)(base + off);
        const float4 b1 = *(const float4*)(base + off + 4);
        const float4 p0 = *(const float4*)(logp + off);
        const float4 p1 = *(const float4*)(logp + off + 4);

        float a[8];
        a[0] = c0.x - b0.x - mean[0];
        a[1] = c0.y - b0.y - mean[1];
        a[2] = c0.z - b0.z - mean[2];
        a[3] = c0.w - b0.w - mean[3];
        a[4] = c1.x - b1.x - mean[4];
        a[5] = c1.y - b1.y - mean[5];
        a[6] = c1.z - b1.z - mean[6];
        a[7] = c1.w - b1.w - mean[7];
        #pragma unroll
        for (int j = 0; j < 8; j++)
            a[j] = fminf(fmaxf(a[j], -CLIPV), CLIPV);

        oacc[0] += a[0] * p0.x;
        oacc[1] += a[1] * p0.y;
        oacc[2] += a[2] * p0.z;
        oacc[3] += a[3] * p0.w;
        oacc[4] += a[4] * p1.x;
        oacc[5] += a[5] * p1.y;
        oacc[6] += a[6] * p1.z;
        oacc[7] += a[7] * p1.w;
    }

    #pragma unroll
    for (int j = 0; j < 8; j++)
        atomicAdd(&obj[col0 + j], oacc[j]);
}

extern "C" void kernel_launch(void* const* d_in, const int* in_sizes, int n_in,
                              void* d_out, int out_size) {
    const float* logp   = (const float*)d_in[0];  // log_probs  [B,T]
    const float* logits = (const float*)d_in[1];  // logits     [B,T,1]
    const float* weight = (const float*)d_in[2];  // weight     [B,T]
    const float* base   = (const float*)d_in[3];  // baselines  [B,T,1]
    float* out = (float*)d_out;

    zero_kernel<<<(Tn + 255) / 256, 256>>>(out);
    phaseA_kernel<<<Bn / ROWS_A, TPB>>>(logits, weight, base, out);
    phaseB_kernel<<<Bn / ROWS_B, TPB>>>(out + Tn, base, logp, out);
}

// round 6
// speedup vs baseline: 1.0700x; 1.0700x over previous
#include <cuda_runtime.h>

// REINFORCE fused kernel, GB300 sm_103a — R3
//
// out[0:T)      = generator_objective  (atomic column reduction)
// out[T:T+B*T)  = cumulative_rewards   (row-major [B,T])
//
// Changes vs R1:
//  - log_sigmoid via MUFU intrinsics (__expf/__logf) : ~5 instr vs ~20
//  - phase A processes 2 rows per iteration (independent scan chains),
//    parity-double-buffered smem -> 1 barrier per 2 rows
//  - __ldcs streaming loads for last-use arrays; default caching for
//    base(read, A) + cum(store, A) so phase B hits them in L2

namespace {
constexpr int   Bn     = 4096;
constexpr int   Tn     = 2048;
constexpr float GAMMA  = 0.99f;
constexpr float CLIPV  = 5.0f;
constexpr int   TPB    = 256;   // thread k owns cols [8k, 8k+8)
constexpr int   ROWS_A = 8;     // rows per block, phase A (4 iterations x 2)
constexpr int   ROWS_B = 8;     // rows per block, phase B
constexpr int   NWARP  = TPB / 32;
}

__device__ float g_colsum[Tn];  // sum over batch of (cum - baseline)

__device__ __forceinline__ float log_sigmoid(float x) {
    // log(sigmoid(x)) = min(x,0) - log1p(exp(-|x|)); fast MUFU path.
    float t = __expf(-fabsf(x));
    return fminf(x, 0.f) - __logf(1.f + t);
}

__global__ void zero_kernel(float* __restrict__ obj) {
    int i = blockIdx.x * blockDim.x + threadIdx.x;
    if (i < Tn) {
        obj[i] = 0.f;
        g_colsum[i] = 0.f;
    }
}

__global__ __launch_bounds__(TPB) void phaseA_kernel(
    const float* __restrict__ logits,
    const float* __restrict__ weight,
    const float* __restrict__ base,
    float* __restrict__ out)
{
    __shared__ float Wsh[2][2][NWARP];   // [parity][row-in-pair][warp]

    const int tid  = threadIdx.x;
    const int lane = tid & 31;
    const int warp = tid >> 5;
    const int col0 = tid * 8;
    const int row0 = blockIdx.x * ROWS_A;

    // gamma powers gp[i] = gamma^i, i in [0,8]
    float gp[9];
    gp[0] = 1.f;
    #pragma unroll
    for (int i = 1; i <= 8; i++) gp[i] = gp[i - 1] * GAMMA;

    const float r8  = gp[8];           // gamma^8  (chunk ratio)
    const float s1  = r8;
    const float s2  = s1 * s1;
    const float s4  = s2 * s2;
    const float s8  = s4 * s4;
    const float s16 = s8 * s8;
    const float r256 = s16 * s16;      // gamma^256 (warp ratio)

    // r8^(31-lane), computed once
    float r8p31 = 1.f;
    for (int i = 0; i < 31 - lane; i++) r8p31 *= r8;

    float dacc[8];
    #pragma unroll
    for (int j = 0; j < 8; j++) dacc[j] = 0.f;

    float* __restrict__ cumout = out + Tn;

    #pragma unroll
    for (int it = 0; it < ROWS_A / 2; ++it) {
        const int parity = it & 1;
        const long offA = (long)(row0 + 2 * it) * Tn + col0;
        const long offB = offA + Tn;

        // ---- issue all streaming loads up front (high MLP) ----
        const float4 lA0 = __ldcs((const float4*)(logits + offA));
        const float4 lA1 = __ldcs((const float4*)(logits + offA + 4));
        const float4 lB0 = __ldcs((const float4*)(logits + offB));
        const float4 lB1 = __ldcs((const float4*)(logits + offB + 4));
        const float4 wA0 = __ldcs((const float4*)(weight + offA));
        const float4 wA1 = __ldcs((const float4*)(weight + offA + 4));
        const float4 wB0 = __ldcs((const float4*)(weight + offB));
        const float4 wB1 = __ldcs((const float4*)(weight + offB + 4));
        // base: default caching (want L2 residency for phase B)
        const float4 bA0 = *(const float4*)(base + offA);
        const float4 bA1 = *(const float4*)(base + offA + 4);
        const float4 bB0 = *(const float4*)(base + offB);
        const float4 bB1 = *(const float4*)(base + offB + 4);

        // ---- weighted rewards ----
        float wrA[8], wrB[8];
        wrA[0] = wA0.x * log_sigmoid(lA0.x);
        wrA[1] = wA0.y * log_sigmoid(lA0.y);
        wrA[2] = wA0.z * log_sigmoid(lA0.z);
        wrA[3] = wA0.w * log_sigmoid(lA0.w);
        wrA[4] = wA1.x * log_sigmoid(lA1.x);
        wrA[5] = wA1.y * log_sigmoid(lA1.y);
        wrA[6] = wA1.z * log_sigmoid(lA1.z);
        wrA[7] = wA1.w * log_sigmoid(lA1.w);
        wrB[0] = wB0.x * log_sigmoid(lB0.x);
        wrB[1] = wB0.y * log_sigmoid(lB0.y);
        wrB[2] = wB0.z * log_sigmoid(lB0.z);
        wrB[3] = wB0.w * log_sigmoid(lB0.w);
        wrB[4] = wB1.x * log_sigmoid(lB1.x);
        wrB[5] = wB1.y * log_sigmoid(lB1.y);
        wrB[6] = wB1.z * log_sigmoid(lB1.z);
        wrB[7] = wB1.w * log_sigmoid(lB1.w);

        // ---- local reverse suffix within each 8-chunk (two indep chains) ----
        float lsA[8], lsB[8];
        lsA[7] = wrA[7];
        lsB[7] = wrB[7];
        #pragma unroll
        for (int j = 6; j >= 0; j--) {
            lsA[j] = wrA[j] + GAMMA * lsA[j + 1];
            lsB[j] = wrB[j] + GAMMA * lsB[j + 1];
        }

        // ---- warp inclusive suffix scans, ratio gamma^8, interleaved ----
        float vA = lsA[0], vB = lsB[0];
        {
            float oA, oB;
            oA = __shfl_down_sync(0xffffffffu, vA, 1);
            oB = __shfl_down_sync(0xffffffffu, vB, 1);
            if (lane + 1 < 32)  { vA += s1 * oA;  vB += s1 * oB; }
            oA = __shfl_down_sync(0xffffffffu, vA, 2);
            oB = __shfl_down_sync(0xffffffffu, vB, 2);
            if (lane + 2 < 32)  { vA += s2 * oA;  vB += s2 * oB; }
            oA = __shfl_down_sync(0xffffffffu, vA, 4);
            oB = __shfl_down_sync(0xffffffffu, vB, 4);
            if (lane + 4 < 32)  { vA += s4 * oA;  vB += s4 * oB; }
            oA = __shfl_down_sync(0xffffffffu, vA, 8);
            oB = __shfl_down_sync(0xffffffffu, vB, 8);
            if (lane + 8 < 32)  { vA += s8 * oA;  vB += s8 * oB; }
            oA = __shfl_down_sync(0xffffffffu, vA, 16);
            oB = __shfl_down_sync(0xffffffffu, vB, 16);
            if (lane + 16 < 32) { vA += s16 * oA; vB += s16 * oB; }
        }
        float vnA = __shfl_down_sync(0xffffffffu, vA, 1);
        float vnB = __shfl_down_sync(0xffffffffu, vB, 1);
        if (lane == 31) { vnA = 0.f; vnB = 0.f; }

        if (lane == 0) {
            Wsh[parity][0][warp] = vA;   // warp total (chunk 0 inclusive suffix)
            Wsh[parity][1][warp] = vB;
        }
        __syncthreads();   // one barrier per 2 rows; WAR handled by parity

        // inclusive suffix over LATER warps, ratio gamma^256
        float swnA = 0.f, swnB = 0.f;
        for (int u = NWARP - 1; u > warp; u--) {
            swnA = Wsh[parity][0][u] + r256 * swnA;
            swnB = Wsh[parity][1][u] + r256 * swnB;
        }

        // carry into this chunk = full cum at time (col0 + 8)
        const float CA = vnA + r8p31 * swnA;
        const float CB = vnB + r8p31 * swnB;

        float cmA[8], cmB[8];
        #pragma unroll
        for (int j = 0; j < 8; j++) {
            cmA[j] = lsA[j] + gp[8 - j] * CA;
            cmB[j] = lsB[j] + gp[8 - j] * CB;
        }

        *(float4*)(cumout + offA)     = make_float4(cmA[0], cmA[1], cmA[2], cmA[3]);
        *(float4*)(cumout + offA + 4) = make_float4(cmA[4], cmA[5], cmA[6], cmA[7]);
        *(float4*)(cumout + offB)     = make_float4(cmB[0], cmB[1], cmB[2], cmB[3]);
        *(float4*)(cumout + offB + 4) = make_float4(cmB[4], cmB[5], cmB[6], cmB[7]);

        dacc[0] += (cmA[0] - bA0.x) + (cmB[0] - bB0.x);
        dacc[1] += (cmA[1] - bA0.y) + (cmB[1] - bB0.y);
        dacc[2] += (cmA[2] - bA0.z) + (cmB[2] - bB0.z);
        dacc[3] += (cmA[3] - bA0.w) + (cmB[3] - bB0.w);
        dacc[4] += (cmA[4] - bA1.x) + (cmB[4] - bB1.x);
        dacc[5] += (cmA[5] - bA1.y) + (cmB[5] - bB1.y);
        dacc[6] += (cmA[6] - bA1.z) + (cmB[6] - bB1.z);
        dacc[7] += (cmA[7] - bA1.w) + (cmB[7] - bB1.w);
    }

    #pragma unroll
    for (int j = 0; j < 8; j++)
        atomicAdd(&g_colsum[col0 + j], dacc[j]);
}

__global__ __launch_bounds__(TPB) void phaseB_kernel(
    const float* __restrict__ cum,
    const float* __restrict__ base,
    const float* __restrict__ logp,
    float* __restrict__ obj)
{
    const int tid  = threadIdx.x;
    const int col0 = tid * 8;
    const int row0 = blockIdx.x * ROWS_B;

    float mean[8];
    #pragma unroll
    for (int j = 0; j < 8; j++) mean[j] = g_colsum[col0 + j] * (1.f / Bn);

    float oacc[8];
    #pragma unroll
    for (int j = 0; j < 8; j++) oacc[j] = 0.f;

    #pragma unroll 2
    for (int r = 0; r < ROWS_B; r++) {
        const long off = (long)(row0 + r) * Tn + col0;

        // all last-use: evict-first
        const float4 c0 = __ldcs((const float4*)(cum + off));
        const float4 c1 = __ldcs((const float4*)(cum + off + 4));
        const float4 b0 = __ldcs((const float4*)(base + off));
        const float4 b1 = __ldcs((const float4*)(base + off + 4));
        const float4 p0 = __ldcs((const float4*)(logp + off));
        const float4 p1 = __ldcs((const float4*)(logp + off + 4));

        float a[8];
        a[0] = c0.x - b0.x - mean[0];
        a[1] = c0.y - b0.y - mean[1];
        a[2] = c0.z - b0.z - mean[2];
        a[3] = c0.w - b0.w - mean[3];
        a[4] = c1.x - b1.x - mean[4];
        a[5] = c1.y - b1.y - mean[5];
        a[6] = c1.z - b1.z - mean[6];
        a[7] = c1.w - b1.w - mean[7];
        #pragma unroll
        for (int j = 0; j < 8; j++)
            a[j] = fminf(fmaxf(a[j], -CLIPV), CLIPV);

        oacc[0] += a[0] * p0.x;
        oacc[1] += a[1] * p0.y;
        oacc[2] += a[2] * p0.z;
        oacc[3] += a[3] * p0.w;
        oacc[4] += a[4] * p1.x;
        oacc[5] += a[5] * p1.y;
        oacc[6] += a[6] * p1.z;
        oacc[7] += a[7] * p1.w;
    }

    #pragma unroll
    for (int j = 0; j < 8; j++)
        atomicAdd(&obj[col0 + j], oacc[j]);
}

extern "C" void kernel_launch(void* const* d_in, const int* in_sizes, int n_in,
                              void* d_out, int out_size) {
    const float* logp   = (const float*)d_in[0];  // log_probs  [B,T]
    const float* logits = (const float*)d_in[1];  // logits     [B,T,1]
    const float* weight = (const float*)d_in[2];  // weight     [B,T]
    const float* base   = (const float*)d_in[3];  // baselines  [B,T,1]
    float* out = (float*)d_out;

    zero_kernel<<<(Tn + 255) / 256, 256>>>(out);
    phaseA_kernel<<<Bn / ROWS_A, TPB>>>(logits, weight, base, out);
    phaseB_kernel<<<Bn / ROWS_B, TPB>>>(out + Tn, base, logp, out);
}

// round 7
// speedup vs baseline: 1.7611x; 1.6458x over previous
#include <cuda_runtime.h>

// REINFORCE fused kernel, GB300 sm_103a — R6
//
// out[0:T)      = generator_objective
// out[T:T+B*T)  = cumulative_rewards (row-major [B,T])
//
// 4 kernels, NO atomics, NO zero kernel:
//   phaseA      : per-row reverse discounted suffix scan (4 elems/thread,
//                 TPB=512, 1-row prefetch pipeline), writes cum + per-block
//                 partial colsum(cum - base) to scratch (plain stores).
//   reduce_mean : sums 512 partials -> g_mean[T]
//   phaseB      : centered clipped advantage * log_probs, per-block partial
//                 column sums to scratch.
//   reduce_obj  : sums 256 partials -> out[0:T)

namespace {
constexpr int   Bn     = 4096;
constexpr int   Tn     = 2048;
constexpr float GAMMA  = 0.99f;
constexpr float CLIPV  = 5.0f;
constexpr int   TPB    = 512;    // thread k owns cols [4k, 4k+4)
constexpr int   ROWS_A = 8;      // rows per block, phase A
constexpr int   ROWS_B = 16;     // rows per block, phase B
constexpr int   NPA    = Bn / ROWS_A;   // 512 phase-A blocks
constexpr int   NPB    = Bn / ROWS_B;   // 256 phase-B blocks
constexpr int   NWARP  = TPB / 32;      // 16
}

__device__ float g_partA[NPA][Tn];   // per-block partial colsum(cum - base)
__device__ float g_partB[NPB][Tn];   // per-block partial objective
__device__ float g_mean[Tn];         // batch mean of (cum - base)

__device__ __forceinline__ float log_sigmoid(float x) {
    float t = __expf(-fabsf(x));
    return fminf(x, 0.f) - __logf(1.f + t);
}

__global__ __launch_bounds__(TPB) void phaseA_kernel(
    const float* __restrict__ logits,
    const float* __restrict__ weight,
    const float* __restrict__ base,
    float* __restrict__ cumout)
{
    __shared__ float Wsh[2][NWARP];

    const int tid  = threadIdx.x;
    const int lane = tid & 31;
    const int warp = tid >> 5;
    const int col0 = tid * 4;
    const int row0 = blockIdx.x * ROWS_A;

    // gamma powers
    const float g1 = GAMMA;
    const float g2 = g1 * g1;
    const float g3 = g2 * g1;
    const float g4 = g2 * g2;          // chunk ratio
    const float w1  = g4;
    const float w2  = w1 * w1;         // gamma^8
    const float w4  = w2 * w2;         // gamma^16
    const float w8  = w4 * w4;         // gamma^32
    const float w16 = w8 * w8;         // gamma^64
    const float r128 = w16 * w16;      // warp ratio gamma^128

    // (gamma^4)^(31-lane)
    float r4p31 = 1.f;
    for (int i = 0; i < 31 - lane; i++) r4p31 *= g4;

    float d0 = 0.f, d1 = 0.f, d2 = 0.f, d3 = 0.f;

    long off = (long)row0 * Tn + col0;

    // prefetch row 0
    float4 lv = __ldcs((const float4*)(logits + off));
    float4 wv = __ldcs((const float4*)(weight + off));
    float4 bv = *(const float4*)(base + off);

    #pragma unroll
    for (int r = 0; r < ROWS_A; ++r) {
        const float4 l = lv, w = wv, b = bv;
        const long offc = off;
        if (r + 1 < ROWS_A) {
            off += Tn;
            lv = __ldcs((const float4*)(logits + off));
            wv = __ldcs((const float4*)(weight + off));
            bv = *(const float4*)(base + off);
        }

        // weighted rewards + local reverse suffix (chunk of 4)
        const float ls3 = w.w * log_sigmoid(l.w);
        const float ls2 = w.z * log_sigmoid(l.z) + g1 * ls3;
        const float ls1 = w.y * log_sigmoid(l.y) + g1 * ls2;
        const float ls0 = w.x * log_sigmoid(l.x) + g1 * ls1;

        // warp inclusive suffix scan over chunk heads, ratio gamma^4
        float v = ls0;
        float o;
        o = __shfl_down_sync(0xffffffffu, v, 1);  if (lane < 31) v += w1  * o;
        o = __shfl_down_sync(0xffffffffu, v, 2);  if (lane < 30) v += w2  * o;
        o = __shfl_down_sync(0xffffffffu, v, 4);  if (lane < 28) v += w4  * o;
        o = __shfl_down_sync(0xffffffffu, v, 8);  if (lane < 24) v += w8  * o;
        o = __shfl_down_sync(0xffffffffu, v, 16); if (lane < 16) v += w16 * o;
        float vn = __shfl_down_sync(0xffffffffu, v, 1);
        if (lane == 31) vn = 0.f;

        const int par = r & 1;
        if (lane == 0) Wsh[par][warp] = v;   // warp-span cum at warp start
        __syncthreads();                     // 1 barrier/row; parity = WAR safe

        // inclusive suffix over later warps, ratio gamma^128
        float swn = 0.f;
        #pragma unroll
        for (int u = NWARP - 1; u >= 1; --u)
            if (u > warp) swn = Wsh[par][u] + r128 * swn;

        // carry = full cum at col0+4
        const float C = vn + r4p31 * swn;

        const float c0 = ls0 + g4 * C;
        const float c1 = ls1 + g3 * C;
        const float c2 = ls2 + g2 * C;
        const float c3 = ls3 + g1 * C;

        *(float4*)(cumout + offc) = make_float4(c0, c1, c2, c3);

        d0 += c0 - b.x;
        d1 += c1 - b.y;
        d2 += c2 - b.z;
        d3 += c3 - b.w;
    }

    *(float4*)(&g_partA[blockIdx.x][col0]) = make_float4(d0, d1, d2, d3);
}

__global__ __launch_bounds__(256) void reduce_mean_kernel() {
    const int t = blockIdx.x * 256 + threadIdx.x;   // 2048 threads
    float s0 = 0.f, s1 = 0.f, s2 = 0.f, s3 = 0.f;
    #pragma unroll 4
    for (int p = 0; p < NPA; p += 4) {
        s0 += g_partA[p + 0][t];
        s1 += g_partA[p + 1][t];
        s2 += g_partA[p + 2][t];
        s3 += g_partA[p + 3][t];
    }
    g_mean[t] = ((s0 + s1) + (s2 + s3)) * (1.f / Bn);
}

__global__ __launch_bounds__(TPB) void phaseB_kernel(
    const float* __restrict__ cum,
    const float* __restrict__ base,
    const float* __restrict__ logp)
{
    const int tid  = threadIdx.x;
    const int col0 = tid * 4;
    const int row0 = blockIdx.x * ROWS_B;

    const float4 m = *(const float4*)(g_mean + col0);

    float o0 = 0.f, o1 = 0.f, o2 = 0.f, o3 = 0.f;

    long off = (long)row0 * Tn + col0;

    // prefetch row 0
    float4 cv = *(const float4*)(cum + off);
    float4 bv = *(const float4*)(base + off);
    float4 pv = __ldcs((const float4*)(logp + off));

    #pragma unroll 4
    for (int r = 0; r < ROWS_B; ++r) {
        const float4 c = cv, b = bv, p = pv;
        if (r + 1 < ROWS_B) {
            off += Tn;
            cv = *(const float4*)(cum + off);
            bv = *(const float4*)(base + off);
            pv = __ldcs((const float4*)(logp + off));
        }

        float a0 = c.x - b.x - m.x;
        float a1 = c.y - b.y - m.y;
        float a2 = c.z - b.z - m.z;
        float a3 = c.w - b.w - m.w;
        a0 = fminf(fmaxf(a0, -CLIPV), CLIPV);
        a1 = fminf(fmaxf(a1, -CLIPV), CLIPV);
        a2 = fminf(fmaxf(a2, -CLIPV), CLIPV);
        a3 = fminf(fmaxf(a3, -CLIPV), CLIPV);

        o0 += a0 * p.x;
        o1 += a1 * p.y;
        o2 += a2 * p.z;
        o3 += a3 * p.w;
    }

    *(float4*)(&g_partB[blockIdx.x][col0]) = make_float4(o0, o1, o2, o3);
}

__global__ __launch_bounds__(256) void reduce_obj_kernel(float* __restrict__ obj) {
    const int t = blockIdx.x * 256 + threadIdx.x;   // 2048 threads
    float s0 = 0.f, s1 = 0.f, s2 = 0.f, s3 = 0.f;
    #pragma unroll 4
    for (int p = 0; p < NPB; p += 4) {
        s0 += g_partB[p + 0][t];
        s1 += g_partB[p + 1][t];
        s2 += g_partB[p + 2][t];
        s3 += g_partB[p + 3][t];
    }
    obj[t] = (s0 + s1) + (s2 + s3);
}

extern "C" void kernel_launch(void* const* d_in, const int* in_sizes, int n_in,
                              void* d_out, int out_size) {
    const float* logp   = (const float*)d_in[0];  // log_probs  [B,T]
    const float* logits = (const float*)d_in[1];  // logits     [B,T,1]
    const float* weight = (const float*)d_in[2];  // weight     [B,T]
    const float* base   = (const float*)d_in[3];  // baselines  [B,T,1]
    float* out = (float*)d_out;

    phaseA_kernel<<<NPA, TPB>>>(logits, weight, base, out + Tn);
    reduce_mean_kernel<<<Tn / 256, 256>>>();
    phaseB_kernel<<<NPB, TPB>>>(out + Tn, base, logp);
    reduce_obj_kernel<<<Tn / 256, 256>>>(out);
}

// round 8
// speedup vs baseline: 2.1975x; 1.2478x over previous
#include <cuda_runtime.h>

// REINFORCE fused kernel, GB300 sm_103a — R7
//
// out[0:T)      = generator_objective
// out[T:T+B*T)  = cumulative_rewards (row-major [B,T])
//
// 4 kernels, NO atomics:
//   phaseA      : per-row reverse discounted suffix scan (4 elems/thread,
//                 TPB=512, 1-row prefetch pipeline), writes cum + per-block
//                 partial colsum(cum - base) to scratch.
//   reduce_mean : 64 blocks x 16 warps, coalesced partial reduction -> g_mean
//   phaseB      : centered clipped advantage * log_probs, per-block partials.
//   reduce_obj  : same shape as reduce_mean -> out[0:T)

namespace {
constexpr int   Bn     = 4096;
constexpr int   Tn     = 2048;
constexpr float GAMMA  = 0.99f;
constexpr float CLIPV  = 5.0f;
constexpr int   TPB    = 512;    // thread k owns cols [4k, 4k+4)
constexpr int   ROWS_A = 8;      // rows per block, phase A
constexpr int   ROWS_B = 16;     // rows per block, phase B
constexpr int   NPA    = Bn / ROWS_A;   // 512 phase-A blocks
constexpr int   NPB    = Bn / ROWS_B;   // 256 phase-B blocks
constexpr int   NWARP  = TPB / 32;      // 16
}

__device__ float g_partA[NPA][Tn];   // per-block partial colsum(cum - base)
__device__ float g_partB[NPB][Tn];   // per-block partial objective
__device__ float g_mean[Tn];         // batch mean of (cum - base)

__device__ __forceinline__ float log_sigmoid(float x) {
    float t = __expf(-fabsf(x));
    return fminf(x, 0.f) - __logf(1.f + t);
}

__global__ __launch_bounds__(TPB) void phaseA_kernel(
    const float* __restrict__ logits,
    const float* __restrict__ weight,
    const float* __restrict__ base,
    float* __restrict__ cumout)
{
    __shared__ float Wsh[2][NWARP];

    const int tid  = threadIdx.x;
    const int lane = tid & 31;
    const int warp = tid >> 5;
    const int col0 = tid * 4;
    const int row0 = blockIdx.x * ROWS_A;

    // gamma powers
    const float g1 = GAMMA;
    const float g2 = g1 * g1;
    const float g3 = g2 * g1;
    const float g4 = g2 * g2;          // chunk ratio
    const float w1  = g4;
    const float w2  = w1 * w1;         // gamma^8
    const float w4  = w2 * w2;         // gamma^16
    const float w8  = w4 * w4;         // gamma^32
    const float w16 = w8 * w8;         // gamma^64
    const float r128 = w16 * w16;      // warp ratio gamma^128

    // (gamma^4)^(31-lane)
    float r4p31 = 1.f;
    for (int i = 0; i < 31 - lane; i++) r4p31 *= g4;

    float d0 = 0.f, d1 = 0.f, d2 = 0.f, d3 = 0.f;

    long off = (long)row0 * Tn + col0;

    // prefetch row 0
    float4 lv = __ldcs((const float4*)(logits + off));
    float4 wv = __ldcs((const float4*)(weight + off));
    float4 bv = *(const float4*)(base + off);

    #pragma unroll
    for (int r = 0; r < ROWS_A; ++r) {
        const float4 l = lv, w = wv, b = bv;
        const long offc = off;
        if (r + 1 < ROWS_A) {
            off += Tn;
            lv = __ldcs((const float4*)(logits + off));
            wv = __ldcs((const float4*)(weight + off));
            bv = *(const float4*)(base + off);
        }

        // weighted rewards + local reverse suffix (chunk of 4)
        const float ls3 = w.w * log_sigmoid(l.w);
        const float ls2 = w.z * log_sigmoid(l.z) + g1 * ls3;
        const float ls1 = w.y * log_sigmoid(l.y) + g1 * ls2;
        const float ls0 = w.x * log_sigmoid(l.x) + g1 * ls1;

        // warp inclusive suffix scan over chunk heads, ratio gamma^4
        float v = ls0;
        float o;
        o = __shfl_down_sync(0xffffffffu, v, 1);  if (lane < 31) v += w1  * o;
        o = __shfl_down_sync(0xffffffffu, v, 2);  if (lane < 30) v += w2  * o;
        o = __shfl_down_sync(0xffffffffu, v, 4);  if (lane < 28) v += w4  * o;
        o = __shfl_down_sync(0xffffffffu, v, 8);  if (lane < 24) v += w8  * o;
        o = __shfl_down_sync(0xffffffffu, v, 16); if (lane < 16) v += w16 * o;
        float vn = __shfl_down_sync(0xffffffffu, v, 1);
        if (lane == 31) vn = 0.f;

        const int par = r & 1;
        if (lane == 0) Wsh[par][warp] = v;   // warp-span cum at warp start
        __syncthreads();                     // 1 barrier/row; parity = WAR safe

        // inclusive suffix over later warps, ratio gamma^128
        float swn = 0.f;
        #pragma unroll
        for (int u = NWARP - 1; u >= 1; --u)
            if (u > warp) swn = Wsh[par][u] + r128 * swn;

        // carry = full cum at col0+4
        const float C = vn + r4p31 * swn;

        const float c0 = ls0 + g4 * C;
        const float c1 = ls1 + g3 * C;
        const float c2 = ls2 + g2 * C;
        const float c3 = ls3 + g1 * C;

        *(float4*)(cumout + offc) = make_float4(c0, c1, c2, c3);

        d0 += c0 - b.x;
        d1 += c1 - b.y;
        d2 += c2 - b.z;
        d3 += c3 - b.w;
    }

    *(float4*)(&g_partA[blockIdx.x][col0]) = make_float4(d0, d1, d2, d3);
}

// 64 blocks x 512 threads. Block owns 32 columns; warp w sums partials
// p = w, w+16, ... (coalesced 128B rows), cross-warp combine in padded smem.
__global__ __launch_bounds__(512) void reduce_mean_kernel() {
    __shared__ float sh[16][33];
    const int lane = threadIdx.x & 31;
    const int w    = threadIdx.x >> 5;
    const int col  = blockIdx.x * 32 + lane;

    float s = 0.f;
    #pragma unroll 8
    for (int p = w; p < NPA; p += 16)
        s += g_partA[p][col];
    sh[w][lane] = s;
    __syncthreads();

    if (w == 0) {
        float t = 0.f;
        #pragma unroll
        for (int u = 0; u < 16; ++u) t += sh[u][lane];
        g_mean[col] = t * (1.f / Bn);
    }
}

__global__ __launch_bounds__(TPB) void phaseB_kernel(
    const float* __restrict__ cum,
    const float* __restrict__ base,
    const float* __restrict__ logp)
{
    const int tid  = threadIdx.x;
    const int col0 = tid * 4;
    const int row0 = blockIdx.x * ROWS_B;

    const float4 m = *(const float4*)(g_mean + col0);

    float o0 = 0.f, o1 = 0.f, o2 = 0.f, o3 = 0.f;

    long off = (long)row0 * Tn + col0;

    // prefetch row 0
    float4 cv = *(const float4*)(cum + off);
    float4 bv = *(const float4*)(base + off);
    float4 pv = __ldcs((const float4*)(logp + off));

    #pragma unroll 4
    for (int r = 0; r < ROWS_B; ++r) {
        const float4 c = cv, b = bv, p = pv;
        if (r + 1 < ROWS_B) {
            off += Tn;
            cv = *(const float4*)(cum + off);
            bv = *(const float4*)(base + off);
            pv = __ldcs((const float4*)(logp + off));
        }

        float a0 = c.x - b.x - m.x;
        float a1 = c.y - b.y - m.y;
        float a2 = c.z - b.z - m.z;
        float a3 = c.w - b.w - m.w;
        a0 = fminf(fmaxf(a0, -CLIPV), CLIPV);
        a1 = fminf(fmaxf(a1, -CLIPV), CLIPV);
        a2 = fminf(fmaxf(a2, -CLIPV), CLIPV);
        a3 = fminf(fmaxf(a3, -CLIPV), CLIPV);

        o0 += a0 * p.x;
        o1 += a1 * p.y;
        o2 += a2 * p.z;
        o3 += a3 * p.w;
    }

    *(float4*)(&g_partB[blockIdx.x][col0]) = make_float4(o0, o1, o2, o3);
}

__global__ __launch_bounds__(512) void reduce_obj_kernel(float* __restrict__ obj) {
    __shared__ float sh[16][33];
    const int lane = threadIdx.x & 31;
    const int w    = threadIdx.x >> 5;
    const int col  = blockIdx.x * 32 + lane;

    float s = 0.f;
    #pragma unroll 8
    for (int p = w; p < NPB; p += 16)
        s += g_partB[p][col];
    sh[w][lane] = s;
    __syncthreads();

    if (w == 0) {
        float t = 0.f;
        #pragma unroll
        for (int u = 0; u < 16; ++u) t += sh[u][lane];
        obj[col] = t;
    }
}

extern "C" void kernel_launch(void* const* d_in, const int* in_sizes, int n_in,
                              void* d_out, int out_size) {
    const float* logp   = (const float*)d_in[0];  // log_probs  [B,T]
    const float* logits = (const float*)d_in[1];  // logits     [B,T,1]
    const float* weight = (const float*)d_in[2];  // weight     [B,T]
    const float* base   = (const float*)d_in[3];  // baselines  [B,T,1]
    float* out = (float*)d_out;

    phaseA_kernel<<<NPA, TPB>>>(logits, weight, base, out + Tn);
    reduce_mean_kernel<<<Tn / 32, 512>>>();
    phaseB_kernel<<<NPB, TPB>>>(out + Tn, base, logp);
    reduce_obj_kernel<<<Tn / 32, 512>>>(out);
}